// round 2
// baseline (speedup 1.0000x reference)
#include <cuda_runtime.h>

#define NSEQ 12800
#define TSTEPS 512

typedef unsigned long long u64;

// ---------- packed f32x2 + fast-math helpers ----------
__device__ __forceinline__ u64 pk2(float lo, float hi) {
    u64 u; asm("mov.b64 %0, {%1,%2};" : "=l"(u) : "f"(lo), "f"(hi)); return u;
}
__device__ __forceinline__ float2 upk2(u64 u) {
    float2 v; asm("mov.b64 {%0,%1}, %2;" : "=f"(v.x), "=f"(v.y) : "l"(u)); return v;
}
__device__ __forceinline__ u64 ffma2(u64 a, u64 b, u64 c) {
    u64 d; asm("fma.rn.f32x2 %0, %1, %2, %3;" : "=l"(d) : "l"(a), "l"(b), "l"(c)); return d;
}
__device__ __forceinline__ float rcp_a(float x) {
    float r; asm("rcp.approx.f32 %0, %1;" : "=f"(r) : "f"(x)); return r;
}
__device__ __forceinline__ float ex2_a(float x) {
    float r; asm("ex2.approx.f32 %0, %1;" : "=f"(r) : "f"(x)); return r;
}
// sigmoid(x) = 1/(1+2^(-x*log2e)); correct saturation at +/-inf (rcp(inf)=0)
__device__ __forceinline__ float sigm(float x) {
    return rcp_a(1.0f + ex2_a(-1.4426950408889634f * x));
}
// tanh(x) = 2/(1+e^(-2x)) - 1
__device__ __forceinline__ float tanh_f(float x) {
    return fmaf(2.0f, rcp_a(1.0f + ex2_a(-2.8853900817779268f * x)), -1.0f);
}

// ---------- global scratch: ping-pong activation buffers, layout (T, N, 16) ----------
__device__ float g_bufA[(size_t)TSTEPS * NSEQ * 16];
__device__ float g_bufB[(size_t)TSTEPS * NSEQ * 16];

template <int IN_PAIRS, bool RAW_IN>
__device__ __forceinline__ void load_x(const float* __restrict__ x_in, int n, int t, u64* dst) {
    const float4* p;
    if (RAW_IN) {
        // raw layout (N, T, 8): 32B contiguous per (n,t)
        p = reinterpret_cast<const float4*>(x_in + (size_t)n * 4096 + (size_t)t * 8);
    } else {
        // scratch layout (T, N, 16): 64B contiguous per (t,n)
        p = reinterpret_cast<const float4*>(x_in + ((size_t)t * NSEQ + (size_t)n) * 16);
    }
#pragma unroll
    for (int q = 0; q < IN_PAIRS / 2; q++) {
        float4 v = p[q];
        dst[2 * q]     = pk2(v.x, v.y);
        dst[2 * q + 1] = pk2(v.z, v.w);
    }
}

// One bidirectional-GRU layer. 8 lanes per (seq,dir) scan; lane u owns hidden
// unit u (gate rows u, u+8, u+16). 4 scans per warp. Weights in registers.
// HEAD (layer 3): forward scans only (no stores), fused single-step backward
// GRU at t=T-1 (h0=0), fused lin1 -> LeakyReLU(0.2) -> lin2 head.
template <int IN_PAIRS, bool RAW_IN, bool HEAD>
__global__ void __launch_bounds__(128)
gru_layer_kernel(const float* __restrict__ x_in, float* __restrict__ x_out,
                 const float* __restrict__ Wih, const float* __restrict__ Whh,
                 const float* __restrict__ bih, const float* __restrict__ bhh,
                 int wih_stride,
                 const float* __restrict__ l1w, const float* __restrict__ l1b,
                 const float* __restrict__ l2w, const float* __restrict__ l2b,
                 float* __restrict__ out)
{
    const int IN = IN_PAIRS * 2;
    const int warpG = blockIdx.x * 4 + (threadIdx.x >> 5);
    const int dir = HEAD ? 0 : (warpG / (NSEQ / 4));
    const int wi  = HEAD ? warpG : (warpG % (NSEQ / 4));
    const int u = threadIdx.x & 7;           // hidden unit owned by this lane
    const int g = (threadIdx.x >> 3) & 3;    // scan group within warp
    const int n = wi * 4 + g;                // sequence index

    const float* wih = Wih + dir * wih_stride;
    const float* whh = Whh + dir * 192;
    const float* bi  = bih + dir * 24;
    const float* bh  = bhh + dir * 24;

    u64 wr[IN_PAIRS], wz[IN_PAIRS], wn[IN_PAIRS];
#pragma unroll
    for (int p = 0; p < IN_PAIRS; p++) {
        wr[p] = pk2(wih[(u     ) * IN + 2 * p], wih[(u     ) * IN + 2 * p + 1]);
        wz[p] = pk2(wih[(u +  8) * IN + 2 * p], wih[(u +  8) * IN + 2 * p + 1]);
        wn[p] = pk2(wih[(u + 16) * IN + 2 * p], wih[(u + 16) * IN + 2 * p + 1]);
    }
    u64 ur[4], uz[4], un[4];
#pragma unroll
    for (int p = 0; p < 4; p++) {
        ur[p] = pk2(whh[(u     ) * 8 + 2 * p], whh[(u     ) * 8 + 2 * p + 1]);
        uz[p] = pk2(whh[(u +  8) * 8 + 2 * p], whh[(u +  8) * 8 + 2 * p + 1]);
        un[p] = pk2(whh[(u + 16) * 8 + 2 * p], whh[(u + 16) * 8 + 2 * p + 1]);
    }
    const float br  = bi[u]      + bh[u];
    const float bz  = bi[u + 8]  + bh[u + 8];
    const float bnx = bi[u + 16];
    const float bnh = bh[u + 16];

    float h = 0.0f;
    u64 xc[IN_PAIRS];

    const int t0 = dir ? (TSTEPS - 1) : 0;
    const int dt = dir ? -1 : 1;
    load_x<IN_PAIRS, RAW_IN>(x_in, n, t0, xc);

    int t = t0;
#pragma unroll 1
    for (int s = 0; s < TSTEPS; s++) {
        int tn = (s == TSTEPS - 1) ? t : (t + dt);
        u64 xnext[IN_PAIRS];
        load_x<IN_PAIRS, RAW_IN>(x_in, n, tn, xnext);

        // broadcast h[0..7] of this scan group as packed pairs (8 shfl)
        u64 hp[4];
#pragma unroll
        for (int p = 0; p < 4; p++) {
            float lo = __shfl_sync(0xffffffffu, h, 2 * p,     8);
            float hi = __shfl_sync(0xffffffffu, h, 2 * p + 1, 8);
            hp[p] = pk2(lo, hi);
        }

        u64 ar = pk2(br, 0.0f), az = pk2(bz, 0.0f);
        u64 ax = pk2(bnx, 0.0f), ah = pk2(bnh, 0.0f);
#pragma unroll
        for (int p = 0; p < IN_PAIRS; p++) {
            ar = ffma2(wr[p], xc[p], ar);
            az = ffma2(wz[p], xc[p], az);
            ax = ffma2(wn[p], xc[p], ax);
        }
#pragma unroll
        for (int p = 0; p < 4; p++) {
            ar = ffma2(ur[p], hp[p], ar);
            az = ffma2(uz[p], hp[p], az);
            ah = ffma2(un[p], hp[p], ah);
        }
        float2 vr = upk2(ar), vz = upk2(az), vx = upk2(ax), vh = upk2(ah);
        float r  = sigm(vr.x + vr.y);
        float z  = sigm(vz.x + vz.y);
        float nn = tanh_f(fmaf(r, vh.x + vh.y, vx.x + vx.y));
        h = fmaf(z, h - nn, nn);   // (1-z)*n + z*h

        if (!HEAD) {
            x_out[((size_t)t * NSEQ + (size_t)n) * 16 + dir * 8 + u] = h;
        }

#pragma unroll
        for (int p = 0; p < IN_PAIRS; p++) xc[p] = xnext[p];
        t = tn;
    }

    if (HEAD) {
        // xc now holds x[T-1] (clamped prefetch on the last iteration).
        // Backward-direction GRU single step at t=T-1 with h0 = 0.
        const float* wihB = Wih + wih_stride;
        const float* biB  = bih + 24;
        const float* bhB  = bhh + 24;
#pragma unroll
        for (int p = 0; p < IN_PAIRS; p++) {
            wr[p] = pk2(wihB[(u     ) * IN + 2 * p], wihB[(u     ) * IN + 2 * p + 1]);
            wz[p] = pk2(wihB[(u +  8) * IN + 2 * p], wihB[(u +  8) * IN + 2 * p + 1]);
            wn[p] = pk2(wihB[(u + 16) * IN + 2 * p], wihB[(u + 16) * IN + 2 * p + 1]);
        }
        const float brB  = biB[u]      + bhB[u];
        const float bzB  = biB[u + 8]  + bhB[u + 8];
        const float bnxB = biB[u + 16];
        const float bnhB = bhB[u + 16];

        u64 ar = pk2(brB, 0.0f), az = pk2(bzB, 0.0f), ax = pk2(bnxB, 0.0f);
#pragma unroll
        for (int p = 0; p < IN_PAIRS; p++) {
            ar = ffma2(wr[p], xc[p], ar);
            az = ffma2(wz[p], xc[p], az);
            ax = ffma2(wn[p], xc[p], ax);
        }
        float2 vr = upk2(ar), vz = upk2(az), vx = upk2(ax);
        float r  = sigm(vr.x + vr.y);
        float z  = sigm(vz.x + vz.y);
        float nn = tanh_f(fmaf(r, bnhB, vx.x + vx.y));
        float hb = (1.0f - z) * nn;   // h0 = 0

        // head: gather h_f / h_b across the 8-lane group, lin1 + leaky + lin2
        float mid = l1b[u];
#pragma unroll
        for (int c = 0; c < 8; c++) {
            float hf_c = __shfl_sync(0xffffffffu, h,  c, 8);
            float hb_c = __shfl_sync(0xffffffffu, hb, c, 8);
            mid = fmaf(l1w[u * 16 + c],     hf_c, mid);
            mid = fmaf(l1w[u * 16 + 8 + c], hb_c, mid);
        }
        float act = (mid >= 0.0f) ? mid : 0.2f * mid;

        float o = l2b[u];
#pragma unroll
        for (int c = 0; c < 8; c++) {
            float a_c = __shfl_sync(0xffffffffu, act, c, 8);
            o = fmaf(l2w[u * 8 + c], a_c, o);
        }
        out[(size_t)n * 8 + u] = o;
    }
}

extern "C" void kernel_launch(void* const* d_in, const int* in_sizes, int n_in,
                              void* d_out, int out_size) {
    (void)in_sizes; (void)n_in; (void)out_size;
    const float* raw  = (const float*)d_in[0];
    const float* Wih0 = (const float*)d_in[1];
    const float* Whh0 = (const float*)d_in[2];
    const float* bih0 = (const float*)d_in[3];
    const float* bhh0 = (const float*)d_in[4];
    const float* WihR = (const float*)d_in[5];   // (3, 2, 24, 16)
    const float* WhhR = (const float*)d_in[6];   // (3, 2, 24, 8)
    const float* bihR = (const float*)d_in[7];   // (3, 2, 24)
    const float* bhhR = (const float*)d_in[8];   // (3, 2, 24)
    const float* l1w  = (const float*)d_in[9];
    const float* l1b  = (const float*)d_in[10];
    const float* l2w  = (const float*)d_in[11];
    const float* l2b  = (const float*)d_in[12];
    float* out = (float*)d_out;

    float *bufA, *bufB;
    cudaGetSymbolAddress((void**)&bufA, g_bufA);
    cudaGetSymbolAddress((void**)&bufB, g_bufB);

    const int BLK_FULL = (2 * NSEQ / 4) / 4;   // 1600 blocks (fwd+bwd)
    const int BLK_HEAD = (NSEQ / 4) / 4;       // 800 blocks (fwd only)

    // Layer 0: raw -> bufA
    gru_layer_kernel<4, true, false><<<BLK_FULL, 128>>>(
        raw, bufA, Wih0, Whh0, bih0, bhh0, 192,
        nullptr, nullptr, nullptr, nullptr, nullptr);

    // Layer 1: bufA -> bufB
    gru_layer_kernel<8, false, false><<<BLK_FULL, 128>>>(
        bufA, bufB, WihR + 0 * 768, WhhR + 0 * 384, bihR + 0 * 48, bhhR + 0 * 48, 384,
        nullptr, nullptr, nullptr, nullptr, nullptr);

    // Layer 2: bufB -> bufA
    gru_layer_kernel<8, false, false><<<BLK_FULL, 128>>>(
        bufB, bufA, WihR + 1 * 768, WhhR + 1 * 384, bihR + 1 * 48, bhhR + 1 * 48, 384,
        nullptr, nullptr, nullptr, nullptr, nullptr);

    // Layer 3 + head: bufA -> out
    gru_layer_kernel<8, false, true><<<BLK_HEAD, 128>>>(
        bufA, nullptr, WihR + 2 * 768, WhhR + 2 * 384, bihR + 2 * 48, bhhR + 2 * 48, 384,
        l1w, l1b, l2w, l2b, out);
}

// round 3
// speedup vs baseline: 1.1210x; 1.1210x over previous
#include <cuda_runtime.h>

#define NSEQ 12800
#define TSTEPS 512

typedef unsigned long long u64;

// ---------- packed f32x2 + fast-math helpers ----------
__device__ __forceinline__ u64 pk2(float lo, float hi) {
    u64 u; asm("mov.b64 %0, {%1,%2};" : "=l"(u) : "f"(lo), "f"(hi)); return u;
}
__device__ __forceinline__ float2 upk2(u64 u) {
    float2 v; asm("mov.b64 {%0,%1}, %2;" : "=f"(v.x), "=f"(v.y) : "l"(u)); return v;
}
__device__ __forceinline__ u64 ffma2(u64 a, u64 b, u64 c) {
    u64 d; asm("fma.rn.f32x2 %0, %1, %2, %3;" : "=l"(d) : "l"(a), "l"(b), "l"(c)); return d;
}
__device__ __forceinline__ float rcp_a(float x) {
    float r; asm("rcp.approx.f32 %0, %1;" : "=f"(r) : "f"(x)); return r;
}
__device__ __forceinline__ float ex2_a(float x) {
    float r; asm("ex2.approx.f32 %0, %1;" : "=f"(r) : "f"(x)); return r;
}
__device__ __forceinline__ void pf_l1(const float* p) {
    asm volatile("prefetch.global.L1 [%0];" :: "l"(p));
}
// sigmoid(x) = 1/(1+2^(-x*log2e)); correct saturation (rcp(inf)=0)
__device__ __forceinline__ float sigm(float x) {
    return rcp_a(1.0f + ex2_a(-1.4426950408889634f * x));
}
// tanh(x) = 2/(1+e^(-2x)) - 1
__device__ __forceinline__ float tanh_f(float x) {
    return fmaf(2.0f, rcp_a(1.0f + ex2_a(-2.8853900817779268f * x)), -1.0f);
}

// ---------- global scratch: ping-pong activation buffers, layout (T, N, 16) ----------
__device__ float g_bufA[(size_t)TSTEPS * NSEQ * 16];
__device__ float g_bufB[(size_t)TSTEPS * NSEQ * 16];

template <bool RAW_IN>
__device__ __forceinline__ const float* xaddr(const float* __restrict__ x, int n, int t) {
    return RAW_IN ? (x + (size_t)n * 4096 + (size_t)t * 8)
                  : (x + ((size_t)t * NSEQ + (size_t)n) * 16);
}

// vector-load IN_PAIRS packed f32x2 values (no mov.b64 repacking)
template <int IN_PAIRS>
__device__ __forceinline__ void load_x2(const float* __restrict__ p, u64* dst) {
    const ulonglong2* q = reinterpret_cast<const ulonglong2*>(p);
#pragma unroll
    for (int i = 0; i < IN_PAIRS / 2; i++) {
        ulonglong2 v = q[i];
        dst[2 * i]     = v.x;
        dst[2 * i + 1] = v.y;
    }
}

// One bidirectional-GRU layer. 8 lanes per (seq,dir) scan; lane u owns hidden
// unit u (gate rows u, u+8, u+16). 4 scans per warp. Weights in registers.
// HEAD (layer 3): forward scans only (no stores), fused single-step backward
// GRU at t=T-1 (h0=0), fused lin1 -> LeakyReLU(0.2) -> lin2 head.
template <int IN_PAIRS, bool RAW_IN, bool HEAD>
__global__ void __launch_bounds__(128)
gru_layer_kernel(const float* __restrict__ x_in, float* __restrict__ x_out,
                 const float* __restrict__ Wih, const float* __restrict__ Whh,
                 const float* __restrict__ bih, const float* __restrict__ bhh,
                 int wih_stride,
                 const float* __restrict__ l1w, const float* __restrict__ l1b,
                 const float* __restrict__ l2w, const float* __restrict__ l2b,
                 float* __restrict__ out)
{
    const int IN = IN_PAIRS * 2;
    const int warpG = blockIdx.x * 4 + (threadIdx.x >> 5);
    const int dir = HEAD ? 0 : (warpG / (NSEQ / 4));
    const int wi  = HEAD ? warpG : (warpG % (NSEQ / 4));
    const int u = threadIdx.x & 7;           // hidden unit owned by this lane
    const int g = (threadIdx.x >> 3) & 3;    // scan group within warp
    const int n = wi * 4 + g;                // sequence index

    const float* wih = Wih + dir * wih_stride;
    const float* whh = Whh + dir * 192;
    const float* bi  = bih + dir * 24;
    const float* bh  = bhh + dir * 24;

    u64 wr[IN_PAIRS], wz[IN_PAIRS], wn[IN_PAIRS];
#pragma unroll
    for (int p = 0; p < IN_PAIRS; p++) {
        wr[p] = pk2(wih[(u     ) * IN + 2 * p], wih[(u     ) * IN + 2 * p + 1]);
        wz[p] = pk2(wih[(u +  8) * IN + 2 * p], wih[(u +  8) * IN + 2 * p + 1]);
        wn[p] = pk2(wih[(u + 16) * IN + 2 * p], wih[(u + 16) * IN + 2 * p + 1]);
    }
    u64 ur[4], uz[4], un[4];
#pragma unroll
    for (int p = 0; p < 4; p++) {
        ur[p] = pk2(whh[(u     ) * 8 + 2 * p], whh[(u     ) * 8 + 2 * p + 1]);
        uz[p] = pk2(whh[(u +  8) * 8 + 2 * p], whh[(u +  8) * 8 + 2 * p + 1]);
        un[p] = pk2(whh[(u + 16) * 8 + 2 * p], whh[(u + 16) * 8 + 2 * p + 1]);
    }
    // packed bias accumulator seeds (hoisted: bias in low lane, 0 in high)
    const u64 brp  = pk2(bi[u]      + bh[u],      0.0f);
    const u64 bzp  = pk2(bi[u + 8]  + bh[u + 8],  0.0f);
    const u64 bnxp = pk2(bi[u + 16],              0.0f);
    const u64 bnhp = pk2(bh[u + 16],              0.0f);

    float h = 0.0f;
    u64 xc[IN_PAIRS];

    const int t0 = dir ? (TSTEPS - 1) : 0;
    const int dt = dir ? -1 : 1;

    const float* xp = xaddr<RAW_IN>(x_in, n, t0);
    const ptrdiff_t xstep = (RAW_IN ? (ptrdiff_t)8 : (ptrdiff_t)NSEQ * 16) * dt;
    float* op = HEAD ? nullptr
                     : (x_out + ((size_t)t0 * NSEQ + (size_t)n) * 16 + dir * 8 + u);
    const ptrdiff_t ostep = (ptrdiff_t)NSEQ * 16 * dt;

    int t = t0;
#pragma unroll 1
    for (int s = 0; s < TSTEPS; s++) {
        // deep prefetch into L1 (distance 8 steps, clamped to valid range)
        int tp = t + 8 * dt;
        tp = tp < 0 ? 0 : (tp > TSTEPS - 1 ? TSTEPS - 1 : tp);
        pf_l1(xaddr<RAW_IN>(x_in, n, tp));

        load_x2<IN_PAIRS>(xp, xc);

        // broadcast h[0..7] of this scan group as packed pairs (8 shfl)
        u64 hp[4];
#pragma unroll
        for (int p = 0; p < 4; p++) {
            float lo = __shfl_sync(0xffffffffu, h, 2 * p,     8);
            float hi = __shfl_sync(0xffffffffu, h, 2 * p + 1, 8);
            hp[p] = pk2(lo, hi);
        }

        u64 ar = brp, az = bzp, ax = bnxp, ah = bnhp;
#pragma unroll
        for (int p = 0; p < 4; p++) {
            ar = ffma2(ur[p], hp[p], ar);
            az = ffma2(uz[p], hp[p], az);
            ah = ffma2(un[p], hp[p], ah);
        }
#pragma unroll
        for (int p = 0; p < IN_PAIRS; p++) {
            ar = ffma2(wr[p], xc[p], ar);
            az = ffma2(wz[p], xc[p], az);
            ax = ffma2(wn[p], xc[p], ax);
        }
        float2 vr = upk2(ar), vz = upk2(az), vx = upk2(ax), vh = upk2(ah);
        float r  = sigm(vr.x + vr.y);
        float z  = sigm(vz.x + vz.y);
        float nn = tanh_f(fmaf(r, vh.x + vh.y, vx.x + vx.y));
        h = fmaf(z, h - nn, nn);   // (1-z)*n + z*h

        if (!HEAD) {
            *op = h;
            op += ostep;
        }
        xp += xstep;
        t += dt;
    }

    if (HEAD) {
        // xc holds x[T-1] (loaded on the final forward iteration).
        // Backward-direction GRU single step at t=T-1 with h0 = 0.
        const float* wihB = Wih + wih_stride;
        const float* biB  = bih + 24;
        const float* bhB  = bhh + 24;
#pragma unroll
        for (int p = 0; p < IN_PAIRS; p++) {
            wr[p] = pk2(wihB[(u     ) * IN + 2 * p], wihB[(u     ) * IN + 2 * p + 1]);
            wz[p] = pk2(wihB[(u +  8) * IN + 2 * p], wihB[(u +  8) * IN + 2 * p + 1]);
            wn[p] = pk2(wihB[(u + 16) * IN + 2 * p], wihB[(u + 16) * IN + 2 * p + 1]);
        }
        const float brB  = biB[u]      + bhB[u];
        const float bzB  = biB[u + 8]  + bhB[u + 8];
        const float bnxB = biB[u + 16];
        const float bnhB = bhB[u + 16];

        u64 ar = pk2(brB, 0.0f), az = pk2(bzB, 0.0f), ax = pk2(bnxB, 0.0f);
#pragma unroll
        for (int p = 0; p < IN_PAIRS; p++) {
            ar = ffma2(wr[p], xc[p], ar);
            az = ffma2(wz[p], xc[p], az);
            ax = ffma2(wn[p], xc[p], ax);
        }
        float2 vr = upk2(ar), vz = upk2(az), vx = upk2(ax);
        float r  = sigm(vr.x + vr.y);
        float z  = sigm(vz.x + vz.y);
        float nn = tanh_f(fmaf(r, bnhB, vx.x + vx.y));
        float hb = (1.0f - z) * nn;   // h0 = 0

        // head: gather h_f / h_b across the 8-lane group, lin1 + leaky + lin2
        float mid = l1b[u];
#pragma unroll
        for (int c = 0; c < 8; c++) {
            float hf_c = __shfl_sync(0xffffffffu, h,  c, 8);
            float hb_c = __shfl_sync(0xffffffffu, hb, c, 8);
            mid = fmaf(l1w[u * 16 + c],     hf_c, mid);
            mid = fmaf(l1w[u * 16 + 8 + c], hb_c, mid);
        }
        float act = (mid >= 0.0f) ? mid : 0.2f * mid;

        float o = l2b[u];
#pragma unroll
        for (int c = 0; c < 8; c++) {
            float a_c = __shfl_sync(0xffffffffu, act, c, 8);
            o = fmaf(l2w[u * 8 + c], a_c, o);
        }
        out[(size_t)n * 8 + u] = o;
    }
}

extern "C" void kernel_launch(void* const* d_in, const int* in_sizes, int n_in,
                              void* d_out, int out_size) {
    (void)in_sizes; (void)n_in; (void)out_size;
    const float* raw  = (const float*)d_in[0];
    const float* Wih0 = (const float*)d_in[1];
    const float* Whh0 = (const float*)d_in[2];
    const float* bih0 = (const float*)d_in[3];
    const float* bhh0 = (const float*)d_in[4];
    const float* WihR = (const float*)d_in[5];   // (3, 2, 24, 16)
    const float* WhhR = (const float*)d_in[6];   // (3, 2, 24, 8)
    const float* bihR = (const float*)d_in[7];   // (3, 2, 24)
    const float* bhhR = (const float*)d_in[8];   // (3, 2, 24)
    const float* l1w  = (const float*)d_in[9];
    const float* l1b  = (const float*)d_in[10];
    const float* l2w  = (const float*)d_in[11];
    const float* l2b  = (const float*)d_in[12];
    float* out = (float*)d_out;

    float *bufA, *bufB;
    cudaGetSymbolAddress((void**)&bufA, g_bufA);
    cudaGetSymbolAddress((void**)&bufB, g_bufB);

    const int BLK_FULL = (2 * NSEQ / 4) / 4;   // 1600 blocks (fwd+bwd)
    const int BLK_HEAD = (NSEQ / 4) / 4;       // 800 blocks (fwd only)

    // Layer 0: raw -> bufA
    gru_layer_kernel<4, true, false><<<BLK_FULL, 128>>>(
        raw, bufA, Wih0, Whh0, bih0, bhh0, 192,
        nullptr, nullptr, nullptr, nullptr, nullptr);

    // Layer 1: bufA -> bufB
    gru_layer_kernel<8, false, false><<<BLK_FULL, 128>>>(
        bufA, bufB, WihR + 0 * 768, WhhR + 0 * 384, bihR + 0 * 48, bhhR + 0 * 48, 384,
        nullptr, nullptr, nullptr, nullptr, nullptr);

    // Layer 2: bufB -> bufA
    gru_layer_kernel<8, false, false><<<BLK_FULL, 128>>>(
        bufB, bufA, WihR + 1 * 768, WhhR + 1 * 384, bihR + 1 * 48, bhhR + 1 * 48, 384,
        nullptr, nullptr, nullptr, nullptr, nullptr);

    // Layer 3 + head: bufA -> out
    gru_layer_kernel<8, false, true><<<BLK_HEAD, 128>>>(
        bufA, nullptr, WihR + 2 * 768, WhhR + 2 * 384, bihR + 2 * 48, bhhR + 2 * 48, 384,
        l1w, l1b, l2w, l2b, out);
}

// round 4
// speedup vs baseline: 1.5922x; 1.4204x over previous
#include <cuda_runtime.h>

#define NSEQ 12800
#define TSTEPS 512
#define CHUNK_T 16
#define NCHUNK (TSTEPS / CHUNK_T)

typedef unsigned long long u64;

// ---------- packed f32x2 + fast-math helpers ----------
__device__ __forceinline__ u64 pk2(float lo, float hi) {
    u64 u; asm("mov.b64 %0, {%1,%2};" : "=l"(u) : "f"(lo), "f"(hi)); return u;
}
__device__ __forceinline__ float2 upk2(u64 u) {
    float2 v; asm("mov.b64 {%0,%1}, %2;" : "=f"(v.x), "=f"(v.y) : "l"(u)); return v;
}
__device__ __forceinline__ u64 ffma2(u64 a, u64 b, u64 c) {
    u64 d; asm("fma.rn.f32x2 %0, %1, %2, %3;" : "=l"(d) : "l"(a), "l"(b), "l"(c)); return d;
}
__device__ __forceinline__ u64 add2(u64 a, u64 b) {
    u64 d; asm("add.rn.f32x2 %0, %1, %2;" : "=l"(d) : "l"(a), "l"(b)); return d;
}
__device__ __forceinline__ float rcp_a(float x) {
    float r; asm("rcp.approx.f32 %0, %1;" : "=f"(r) : "f"(x)); return r;
}
__device__ __forceinline__ float ex2_a(float x) {
    float r; asm("ex2.approx.f32 %0, %1;" : "=f"(r) : "f"(x)); return r;
}
__device__ __forceinline__ float hsum(u64 a) { float2 v = upk2(a); return v.x + v.y; }

// gate weights pre-scaled by -log2e:       sigm(x) = rcp(1 + ex2(scaled_acc))
// n-gate weights pre-scaled by -2*log2e:   tanh(v) = 2*rcp(1 + ex2(scaled_acc)) - 1
#define KRZ (-1.4426950408889634f)
#define KN  (-2.8853900817779268f)

// ---------- global scratch: ping-pong activation buffers, layout (T, N, 16) ----------
__device__ float g_bufA[(size_t)TSTEPS * NSEQ * 16];
__device__ float g_bufB[(size_t)TSTEPS * NSEQ * 16];

// ---------- cp.async chunk loader ----------
// smem chunk layout: [tt (16)][scan (16)][INF floats, padded row to INF*4+16 bytes]
template <int INF, bool RAW>
__device__ __forceinline__ void issue_chunk(char* sbuf, const float* __restrict__ x_in,
                                            int nb, int c, int dir, int tid) {
    constexpr int SCAN_STRIDE = INF * 4 + 16;
    constexpr int TT_STRIDE = 16 * SCAN_STRIDE;
    constexpr int V_PER_SCAN = INF / 4;               // 16B vectors per scan row
    constexpr int PER_TT = 16 * V_PER_SCAN;
    constexpr int TOTAL = CHUNK_T * PER_TT;
#pragma unroll
    for (int k = 0; k < TOTAL / 128; k++) {
        int j = k * 128 + tid;
        int tt = j / PER_TT;
        int r = j % PER_TT;
        int scan = r / V_PER_SCAN;
        int c16 = r % V_PER_SCAN;
        int t = dir ? (TSTEPS - 1 - (c * CHUNK_T + tt)) : (c * CHUNK_T + tt);
        const float* g = RAW
            ? x_in + (size_t)(nb + scan) * 4096 + (size_t)t * 8 + c16 * 4
            : x_in + ((size_t)t * NSEQ + (size_t)(nb + scan)) * 16 + c16 * 4;
        unsigned s = (unsigned)__cvta_generic_to_shared(
            sbuf + tt * TT_STRIDE + scan * SCAN_STRIDE + c16 * 16);
        asm volatile("cp.async.cg.shared.global [%0], [%1], 16;" :: "r"(s), "l"(g));
    }
}

// One bidirectional-GRU layer. Block = 128 threads = 16 scans (same direction).
// 8 lanes per scan; lane u owns hidden unit u (gate rows u, u+8, u+16).
// x stream staged through double-buffered smem via cp.async, 2 chunks deep.
// HEAD (layer 3): forward scans only, no stores; fused 1-step backward GRU at
// t=T-1 (h0=0) + lin1 -> LeakyReLU(0.2) -> lin2 head.
template <int INF, bool RAW_IN, bool HEAD>
__global__ void __launch_bounds__(128)
gru_layer_kernel(const float* __restrict__ x_in, float* __restrict__ x_out,
                 const float* __restrict__ Wih, const float* __restrict__ Whh,
                 const float* __restrict__ bih, const float* __restrict__ bhh,
                 int wih_stride,
                 const float* __restrict__ l1w, const float* __restrict__ l1b,
                 const float* __restrict__ l2w, const float* __restrict__ l2b,
                 float* __restrict__ out)
{
    constexpr int IN_PAIRS = INF / 2;
    constexpr int SCAN_STRIDE = INF * 4 + 16;
    constexpr int TT_STRIDE = 16 * SCAN_STRIDE;
    constexpr int CHUNK_BYTES = CHUNK_T * TT_STRIDE;

    extern __shared__ char sb[];

    const int tid = threadIdx.x;
    const int dir = HEAD ? 0 : (blockIdx.x / (NSEQ / 16));
    const int nb  = (HEAD ? blockIdx.x : (blockIdx.x % (NSEQ / 16))) * 16;
    const int u = tid & 7;
    const int scan_local = (tid >> 5) * 4 + ((tid >> 3) & 3);
    const int n = nb + scan_local;

    // ---- register weights, pre-scaled ----
    const float* wih = Wih + dir * wih_stride;
    const float* whh = Whh + dir * 192;
    const float* bi  = bih + dir * 24;
    const float* bh  = bhh + dir * 24;

    u64 wr[IN_PAIRS], wz[IN_PAIRS], wn[IN_PAIRS];
#pragma unroll
    for (int p = 0; p < IN_PAIRS; p++) {
        wr[p] = pk2(KRZ * wih[(u     ) * INF + 2 * p], KRZ * wih[(u     ) * INF + 2 * p + 1]);
        wz[p] = pk2(KRZ * wih[(u +  8) * INF + 2 * p], KRZ * wih[(u +  8) * INF + 2 * p + 1]);
        wn[p] = pk2(KN  * wih[(u + 16) * INF + 2 * p], KN  * wih[(u + 16) * INF + 2 * p + 1]);
    }
    u64 ur[4], uz[4], un[4];
#pragma unroll
    for (int p = 0; p < 4; p++) {
        ur[p] = pk2(KRZ * whh[(u     ) * 8 + 2 * p], KRZ * whh[(u     ) * 8 + 2 * p + 1]);
        uz[p] = pk2(KRZ * whh[(u +  8) * 8 + 2 * p], KRZ * whh[(u +  8) * 8 + 2 * p + 1]);
        un[p] = pk2(KN  * whh[(u + 16) * 8 + 2 * p], KN  * whh[(u + 16) * 8 + 2 * p + 1]);
    }
    const u64 brp  = pk2(KRZ * (bi[u]     + bh[u]),     0.0f);
    const u64 bzp  = pk2(KRZ * (bi[u + 8] + bh[u + 8]), 0.0f);
    const u64 bnxp = pk2(KN * bi[u + 16], 0.0f);
    const float bnh_s = KN * bh[u + 16];

    const int t0 = dir ? (TSTEPS - 1) : 0;
    float* op = HEAD ? nullptr
                     : (x_out + ((size_t)t0 * NSEQ + (size_t)n) * 16 + dir * 8 + u);
    const ptrdiff_t ostep = (ptrdiff_t)NSEQ * 16 * (dir ? -1 : 1);

    // ---- prime the pipeline ----
    issue_chunk<INF, RAW_IN>(sb, x_in, nb, 0, dir, tid);
    asm volatile("cp.async.commit_group;" ::: "memory");
    issue_chunk<INF, RAW_IN>(sb + CHUNK_BYTES, x_in, nb, 1, dir, tid);
    asm volatile("cp.async.commit_group;" ::: "memory");

    float h = 0.0f;

#pragma unroll 1
    for (int c = 0; c < NCHUNK; c++) {
        asm volatile("cp.async.wait_group 1;" ::: "memory");
        __syncthreads();
        const char* xrow = sb + (c & 1) * CHUNK_BYTES + scan_local * SCAN_STRIDE;

#pragma unroll
        for (int tt = 0; tt < CHUNK_T; tt++) {
            const ulonglong2* q = reinterpret_cast<const ulonglong2*>(xrow + tt * TT_STRIDE);
            u64 xc[IN_PAIRS];
#pragma unroll
            for (int i = 0; i < IN_PAIRS / 2; i++) {
                ulonglong2 v = q[i];
                xc[2 * i] = v.x; xc[2 * i + 1] = v.y;
            }

            // broadcast h[0..7] of this scan group (8 independent shfl)
            u64 hp[4];
#pragma unroll
            for (int p = 0; p < 4; p++) {
                float lo = __shfl_sync(0xffffffffu, h, 2 * p,     8);
                float hi = __shfl_sync(0xffffffffu, h, 2 * p + 1, 8);
                hp[p] = pk2(lo, hi);
            }

            // x-chains (independent of h) and h-chains (start right after shfl)
            u64 axr = brp, axz = bzp, axn = bnxp;
#pragma unroll
            for (int p = 0; p < IN_PAIRS; p++) {
                axr = ffma2(wr[p], xc[p], axr);
                axz = ffma2(wz[p], xc[p], axz);
                axn = ffma2(wn[p], xc[p], axn);
            }
            u64 ahr = 0ULL, ahz = 0ULL, ahn = 0ULL;
#pragma unroll
            for (int p = 0; p < 4; p++) {
                ahr = ffma2(ur[p], hp[p], ahr);
                ahz = ffma2(uz[p], hp[p], ahz);
                ahn = ffma2(un[p], hp[p], ahn);
            }
            float sr = hsum(add2(axr, ahr));
            float sz = hsum(add2(axz, ahz));
            float sxn = hsum(axn);
            float shn = hsum(ahn) + bnh_s;

            float r = rcp_a(1.0f + ex2_a(sr));                       // sigmoid
            float z = rcp_a(1.0f + ex2_a(sz));                       // sigmoid
            float nn = fmaf(2.0f, rcp_a(1.0f + ex2_a(fmaf(r, shn, sxn))), -1.0f); // tanh
            h = fmaf(z, h - nn, nn);

            if (!HEAD) { *op = h; op += ostep; }
        }
        __syncthreads();
        if (c + 2 < NCHUNK)
            issue_chunk<INF, RAW_IN>(sb + (c & 1) * CHUNK_BYTES, x_in, nb, c + 2, dir, tid);
        asm volatile("cp.async.commit_group;" ::: "memory");
    }

    if (HEAD) {
        // x[T-1] still resident in the last chunk's smem buffer
        const char* xrow = sb + ((NCHUNK - 1) & 1) * CHUNK_BYTES
                         + scan_local * SCAN_STRIDE + (CHUNK_T - 1) * TT_STRIDE;
        const ulonglong2* q = reinterpret_cast<const ulonglong2*>(xrow);
        u64 xc[IN_PAIRS];
#pragma unroll
        for (int i = 0; i < IN_PAIRS / 2; i++) {
            ulonglong2 v = q[i];
            xc[2 * i] = v.x; xc[2 * i + 1] = v.y;
        }

        // backward-direction single step at t=T-1, h0=0 (gh = b_hh)
        const float* wihB = Wih + wih_stride;
        const float* biB  = bih + 24;
        const float* bhB  = bhh + 24;
        u64 br_[IN_PAIRS], bz_[IN_PAIRS], bn_[IN_PAIRS];
#pragma unroll
        for (int p = 0; p < IN_PAIRS; p++) {
            br_[p] = pk2(KRZ * wihB[(u     ) * INF + 2 * p], KRZ * wihB[(u     ) * INF + 2 * p + 1]);
            bz_[p] = pk2(KRZ * wihB[(u +  8) * INF + 2 * p], KRZ * wihB[(u +  8) * INF + 2 * p + 1]);
            bn_[p] = pk2(KN  * wihB[(u + 16) * INF + 2 * p], KN  * wihB[(u + 16) * INF + 2 * p + 1]);
        }
        u64 ar = pk2(KRZ * (biB[u]     + bhB[u]),     0.0f);
        u64 az = pk2(KRZ * (biB[u + 8] + bhB[u + 8]), 0.0f);
        u64 ax = pk2(KN * biB[u + 16], 0.0f);
        const float bnhB = KN * bhB[u + 16];
#pragma unroll
        for (int p = 0; p < IN_PAIRS; p++) {
            ar = ffma2(br_[p], xc[p], ar);
            az = ffma2(bz_[p], xc[p], az);
            ax = ffma2(bn_[p], xc[p], ax);
        }
        float r = rcp_a(1.0f + ex2_a(hsum(ar)));
        float z = rcp_a(1.0f + ex2_a(hsum(az)));
        float nn = fmaf(2.0f, rcp_a(1.0f + ex2_a(fmaf(r, bnhB, hsum(ax)))), -1.0f);
        float hb = (1.0f - z) * nn;

        // head: lin1 + LeakyReLU(0.2) + lin2 over [h_f ; h_b]
        float mid = l1b[u];
#pragma unroll
        for (int cc = 0; cc < 8; cc++) {
            float hf_c = __shfl_sync(0xffffffffu, h,  cc, 8);
            float hb_c = __shfl_sync(0xffffffffu, hb, cc, 8);
            mid = fmaf(l1w[u * 16 + cc],     hf_c, mid);
            mid = fmaf(l1w[u * 16 + 8 + cc], hb_c, mid);
        }
        float act = (mid >= 0.0f) ? mid : 0.2f * mid;

        float o = l2b[u];
#pragma unroll
        for (int cc = 0; cc < 8; cc++) {
            float a_c = __shfl_sync(0xffffffffu, act, cc, 8);
            o = fmaf(l2w[u * 8 + cc], a_c, o);
        }
        out[(size_t)n * 8 + u] = o;
    }
}

extern "C" void kernel_launch(void* const* d_in, const int* in_sizes, int n_in,
                              void* d_out, int out_size) {
    (void)in_sizes; (void)n_in; (void)out_size;
    const float* raw  = (const float*)d_in[0];
    const float* Wih0 = (const float*)d_in[1];
    const float* Whh0 = (const float*)d_in[2];
    const float* bih0 = (const float*)d_in[3];
    const float* bhh0 = (const float*)d_in[4];
    const float* WihR = (const float*)d_in[5];   // (3, 2, 24, 16)
    const float* WhhR = (const float*)d_in[6];   // (3, 2, 24, 8)
    const float* bihR = (const float*)d_in[7];   // (3, 2, 24)
    const float* bhhR = (const float*)d_in[8];   // (3, 2, 24)
    const float* l1w  = (const float*)d_in[9];
    const float* l1b  = (const float*)d_in[10];
    const float* l2w  = (const float*)d_in[11];
    const float* l2b  = (const float*)d_in[12];
    float* out = (float*)d_out;

    float *bufA, *bufB;
    cudaGetSymbolAddress((void**)&bufA, g_bufA);
    cudaGetSymbolAddress((void**)&bufB, g_bufB);

    const int BLK_FULL = 2 * (NSEQ / 16);   // 1600 blocks (fwd + bwd)
    const int BLK_HEAD = NSEQ / 16;         // 800 blocks (fwd only)
    const int SMEM8  = 2 * CHUNK_T * 16 * (8 * 4 + 16);    // 24576
    const int SMEM16 = 2 * CHUNK_T * 16 * (16 * 4 + 16);   // 40960

    // Layer 0: raw -> bufA
    gru_layer_kernel<8, true, false><<<BLK_FULL, 128, SMEM8>>>(
        raw, bufA, Wih0, Whh0, bih0, bhh0, 192,
        nullptr, nullptr, nullptr, nullptr, nullptr);

    // Layer 1: bufA -> bufB
    gru_layer_kernel<16, false, false><<<BLK_FULL, 128, SMEM16>>>(
        bufA, bufB, WihR + 0 * 768, WhhR + 0 * 384, bihR + 0 * 48, bhhR + 0 * 48, 384,
        nullptr, nullptr, nullptr, nullptr, nullptr);

    // Layer 2: bufB -> bufA
    gru_layer_kernel<16, false, false><<<BLK_FULL, 128, SMEM16>>>(
        bufB, bufA, WihR + 1 * 768, WhhR + 1 * 384, bihR + 1 * 48, bhhR + 1 * 48, 384,
        nullptr, nullptr, nullptr, nullptr, nullptr);

    // Layer 3 + head: bufA -> out
    gru_layer_kernel<16, false, true><<<BLK_HEAD, 128, SMEM16>>>(
        bufA, nullptr, WihR + 2 * 768, WhhR + 2 * 384, bihR + 2 * 48, bhhR + 2 * 48, 384,
        l1w, l1b, l2w, l2b, out);
}

// round 5
// speedup vs baseline: 1.9797x; 1.2433x over previous
#include <cuda_runtime.h>

#define NSEQ 12800
#define TSTEPS 512
#define CHUNK_T 16
#define NCHUNK (TSTEPS / CHUNK_T)

typedef unsigned long long u64;

// ---------- packed f32x2 + fast-math helpers ----------
__device__ __forceinline__ u64 pk2(float lo, float hi) {
    u64 u; asm("mov.b64 %0, {%1,%2};" : "=l"(u) : "f"(lo), "f"(hi)); return u;
}
__device__ __forceinline__ float2 upk2(u64 u) {
    float2 v; asm("mov.b64 {%0,%1}, %2;" : "=f"(v.x), "=f"(v.y) : "l"(u)); return v;
}
__device__ __forceinline__ u64 ffma2(u64 a, u64 b, u64 c) {
    u64 d; asm("fma.rn.f32x2 %0, %1, %2, %3;" : "=l"(d) : "l"(a), "l"(b), "l"(c)); return d;
}
__device__ __forceinline__ float tanh_a(float x) {
    float r; asm("tanh.approx.f32 %0, %1;" : "=f"(r) : "f"(x)); return r;
}
__device__ __forceinline__ float hsum(u64 a) { float2 v = upk2(a); return v.x + v.y; }

// r/z gate weights pre-scaled by 0.5: sigmoid(x) = 0.5*tanh(x/2) + 0.5  (1 MUFU)
// n gate: tanh(acc) directly                                            (1 MUFU)
#define KRZ (0.5f)

// ---------- global scratch: ping-pong activation buffers, layout (T, N, 16) ----------
__device__ float g_bufA[(size_t)TSTEPS * NSEQ * 16];
__device__ float g_bufB[(size_t)TSTEPS * NSEQ * 16];

// ---------- cp.async chunk loader ----------
// smem chunk layout: [tt (16)][scan (16)][INF floats, padded row to INF*4+16 bytes]
template <int INF, bool RAW>
__device__ __forceinline__ void issue_chunk(char* sbuf, const float* __restrict__ x_in,
                                            int nb, int c, int dir, int tid) {
    constexpr int SCAN_STRIDE = INF * 4 + 16;
    constexpr int TT_STRIDE = 16 * SCAN_STRIDE;
    constexpr int V_PER_SCAN = INF / 4;               // 16B vectors per scan row
    constexpr int PER_TT = 16 * V_PER_SCAN;
    constexpr int TOTAL = CHUNK_T * PER_TT;
#pragma unroll
    for (int k = 0; k < TOTAL / 128; k++) {
        int j = k * 128 + tid;
        int tt = j / PER_TT;
        int r = j % PER_TT;
        int scan = r / V_PER_SCAN;
        int c16 = r % V_PER_SCAN;
        int t = dir ? (TSTEPS - 1 - (c * CHUNK_T + tt)) : (c * CHUNK_T + tt);
        const float* g = RAW
            ? x_in + (size_t)(nb + scan) * 4096 + (size_t)t * 8 + c16 * 4
            : x_in + ((size_t)t * NSEQ + (size_t)(nb + scan)) * 16 + c16 * 4;
        unsigned s = (unsigned)__cvta_generic_to_shared(
            sbuf + tt * TT_STRIDE + scan * SCAN_STRIDE + c16 * 16);
        asm volatile("cp.async.cg.shared.global [%0], [%1], 16;" :: "r"(s), "l"(g));
    }
}

// One bidirectional-GRU layer. Block = 128 threads = 16 scans (same direction).
// 8 lanes per scan; lane u owns hidden unit u (gate rows u, u+8, u+16).
// x stream staged through double-buffered smem via cp.async, 2 chunks deep.
// HEAD (layer 3): forward scans only, no stores; fused 1-step backward GRU at
// t=T-1 (h0=0) + lin1 -> LeakyReLU(0.2) -> lin2 head.
template <int INF, bool RAW_IN, bool HEAD>
__global__ void __launch_bounds__(128)
gru_layer_kernel(const float* __restrict__ x_in, float* __restrict__ x_out,
                 const float* __restrict__ Wih, const float* __restrict__ Whh,
                 const float* __restrict__ bih, const float* __restrict__ bhh,
                 int wih_stride,
                 const float* __restrict__ l1w, const float* __restrict__ l1b,
                 const float* __restrict__ l2w, const float* __restrict__ l2b,
                 float* __restrict__ out)
{
    constexpr int IN_PAIRS = INF / 2;
    constexpr int SCAN_STRIDE = INF * 4 + 16;
    constexpr int TT_STRIDE = 16 * SCAN_STRIDE;
    constexpr int CHUNK_BYTES = CHUNK_T * TT_STRIDE;

    extern __shared__ char sb[];

    const int tid = threadIdx.x;
    const int dir = HEAD ? 0 : (blockIdx.x / (NSEQ / 16));
    const int nb  = (HEAD ? blockIdx.x : (blockIdx.x % (NSEQ / 16))) * 16;
    const int u = tid & 7;
    const int scan_local = (tid >> 5) * 4 + ((tid >> 3) & 3);
    const int n = nb + scan_local;

    // ---- register weights, pre-scaled ----
    const float* wih = Wih + dir * wih_stride;
    const float* whh = Whh + dir * 192;
    const float* bi  = bih + dir * 24;
    const float* bh  = bhh + dir * 24;

    u64 wr[IN_PAIRS], wz[IN_PAIRS], wn[IN_PAIRS];
#pragma unroll
    for (int p = 0; p < IN_PAIRS; p++) {
        wr[p] = pk2(KRZ * wih[(u     ) * INF + 2 * p], KRZ * wih[(u     ) * INF + 2 * p + 1]);
        wz[p] = pk2(KRZ * wih[(u +  8) * INF + 2 * p], KRZ * wih[(u +  8) * INF + 2 * p + 1]);
        wn[p] = pk2(       wih[(u + 16) * INF + 2 * p],        wih[(u + 16) * INF + 2 * p + 1]);
    }
    u64 ur[4], uz[4], un[4];
#pragma unroll
    for (int p = 0; p < 4; p++) {
        ur[p] = pk2(KRZ * whh[(u     ) * 8 + 2 * p], KRZ * whh[(u     ) * 8 + 2 * p + 1]);
        uz[p] = pk2(KRZ * whh[(u +  8) * 8 + 2 * p], KRZ * whh[(u +  8) * 8 + 2 * p + 1]);
        un[p] = pk2(       whh[(u + 16) * 8 + 2 * p],        whh[(u + 16) * 8 + 2 * p + 1]);
    }
    const u64 brp  = pk2(KRZ * (bi[u]     + bh[u]),     0.0f);
    const u64 bzp  = pk2(KRZ * (bi[u + 8] + bh[u + 8]), 0.0f);
    const u64 bnxp = pk2(bi[u + 16], 0.0f);
    const u64 bnhp = pk2(bh[u + 16], 0.0f);

    const int t0 = dir ? (TSTEPS - 1) : 0;
    float* op = HEAD ? nullptr
                     : (x_out + ((size_t)t0 * NSEQ + (size_t)n) * 16 + dir * 8 + u);
    const ptrdiff_t ostep = (ptrdiff_t)NSEQ * 16 * (dir ? -1 : 1);

    // ---- prime the pipeline ----
    issue_chunk<INF, RAW_IN>(sb, x_in, nb, 0, dir, tid);
    asm volatile("cp.async.commit_group;" ::: "memory");
    issue_chunk<INF, RAW_IN>(sb + CHUNK_BYTES, x_in, nb, 1, dir, tid);
    asm volatile("cp.async.commit_group;" ::: "memory");

    float h = 0.0f;

#pragma unroll 1
    for (int c = 0; c < NCHUNK; c++) {
        asm volatile("cp.async.wait_group 1;" ::: "memory");
        __syncthreads();
        const char* xrow = sb + (c & 1) * CHUNK_BYTES + scan_local * SCAN_STRIDE;

#pragma unroll
        for (int tt = 0; tt < CHUNK_T; tt++) {
            const ulonglong2* q = reinterpret_cast<const ulonglong2*>(xrow + tt * TT_STRIDE);
            u64 xc[IN_PAIRS];
#pragma unroll
            for (int i = 0; i < IN_PAIRS / 2; i++) {
                ulonglong2 v = q[i];
                xc[2 * i] = v.x; xc[2 * i + 1] = v.y;
            }

            // broadcast h[0..7] of this scan group (8 independent shfl)
            u64 hp[4];
#pragma unroll
            for (int p = 0; p < 4; p++) {
                float lo = __shfl_sync(0xffffffffu, h, 2 * p,     8);
                float hi = __shfl_sync(0xffffffffu, h, 2 * p + 1, 8);
                hp[p] = pk2(lo, hi);
            }

            // x-parts (independent of h) accumulate first; h-parts chain after shfl
            u64 ar = brp, az = bzp, axn = bnxp, ahn = bnhp;
#pragma unroll
            for (int p = 0; p < IN_PAIRS; p++) {
                ar  = ffma2(wr[p], xc[p], ar);
                az  = ffma2(wz[p], xc[p], az);
                axn = ffma2(wn[p], xc[p], axn);
            }
#pragma unroll
            for (int p = 0; p < 4; p++) {
                ar  = ffma2(ur[p], hp[p], ar);
                az  = ffma2(uz[p], hp[p], az);
                ahn = ffma2(un[p], hp[p], ahn);
            }
            float r = fmaf(0.5f, tanh_a(hsum(ar)), 0.5f);   // sigmoid
            float z = fmaf(0.5f, tanh_a(hsum(az)), 0.5f);   // sigmoid
            float nn = tanh_a(fmaf(r, hsum(ahn), hsum(axn)));
            h = fmaf(z, h - nn, nn);

            if (!HEAD) { *op = h; op += ostep; }
        }
        __syncthreads();
        if (c + 2 < NCHUNK)
            issue_chunk<INF, RAW_IN>(sb + (c & 1) * CHUNK_BYTES, x_in, nb, c + 2, dir, tid);
        asm volatile("cp.async.commit_group;" ::: "memory");
    }

    if (HEAD) {
        // x[T-1] still resident in the last chunk's smem buffer
        const char* xrow = sb + ((NCHUNK - 1) & 1) * CHUNK_BYTES
                         + scan_local * SCAN_STRIDE + (CHUNK_T - 1) * TT_STRIDE;
        const ulonglong2* q = reinterpret_cast<const ulonglong2*>(xrow);
        u64 xc[IN_PAIRS];
#pragma unroll
        for (int i = 0; i < IN_PAIRS / 2; i++) {
            ulonglong2 v = q[i];
            xc[2 * i] = v.x; xc[2 * i + 1] = v.y;
        }

        // backward-direction single step at t=T-1, h0=0 (gh = b_hh)
        const float* wihB = Wih + wih_stride;
        const float* biB  = bih + 24;
        const float* bhB  = bhh + 24;
        u64 br_[IN_PAIRS], bz_[IN_PAIRS], bn_[IN_PAIRS];
#pragma unroll
        for (int p = 0; p < IN_PAIRS; p++) {
            br_[p] = pk2(KRZ * wihB[(u     ) * INF + 2 * p], KRZ * wihB[(u     ) * INF + 2 * p + 1]);
            bz_[p] = pk2(KRZ * wihB[(u +  8) * INF + 2 * p], KRZ * wihB[(u +  8) * INF + 2 * p + 1]);
            bn_[p] = pk2(       wihB[(u + 16) * INF + 2 * p],        wihB[(u + 16) * INF + 2 * p + 1]);
        }
        u64 ar = pk2(KRZ * (biB[u]     + bhB[u]),     0.0f);
        u64 az = pk2(KRZ * (biB[u + 8] + bhB[u + 8]), 0.0f);
        u64 ax = pk2(biB[u + 16], 0.0f);
        const float bnhB = bhB[u + 16];
#pragma unroll
        for (int p = 0; p < IN_PAIRS; p++) {
            ar = ffma2(br_[p], xc[p], ar);
            az = ffma2(bz_[p], xc[p], az);
            ax = ffma2(bn_[p], xc[p], ax);
        }
        float r = fmaf(0.5f, tanh_a(hsum(ar)), 0.5f);
        float z = fmaf(0.5f, tanh_a(hsum(az)), 0.5f);
        float nn = tanh_a(fmaf(r, bnhB, hsum(ax)));
        float hb = (1.0f - z) * nn;   // h0 = 0

        // head: lin1 + LeakyReLU(0.2) + lin2 over [h_f ; h_b]
        float mid = l1b[u];
#pragma unroll
        for (int cc = 0; cc < 8; cc++) {
            float hf_c = __shfl_sync(0xffffffffu, h,  cc, 8);
            float hb_c = __shfl_sync(0xffffffffu, hb, cc, 8);
            mid = fmaf(l1w[u * 16 + cc],     hf_c, mid);
            mid = fmaf(l1w[u * 16 + 8 + cc], hb_c, mid);
        }
        float act = (mid >= 0.0f) ? mid : 0.2f * mid;

        float o = l2b[u];
#pragma unroll
        for (int cc = 0; cc < 8; cc++) {
            float a_c = __shfl_sync(0xffffffffu, act, cc, 8);
            o = fmaf(l2w[u * 8 + cc], a_c, o);
        }
        out[(size_t)n * 8 + u] = o;
    }
}

extern "C" void kernel_launch(void* const* d_in, const int* in_sizes, int n_in,
                              void* d_out, int out_size) {
    (void)in_sizes; (void)n_in; (void)out_size;
    const float* raw  = (const float*)d_in[0];
    const float* Wih0 = (const float*)d_in[1];
    const float* Whh0 = (const float*)d_in[2];
    const float* bih0 = (const float*)d_in[3];
    const float* bhh0 = (const float*)d_in[4];
    const float* WihR = (const float*)d_in[5];   // (3, 2, 24, 16)
    const float* WhhR = (const float*)d_in[6];   // (3, 2, 24, 8)
    const float* bihR = (const float*)d_in[7];   // (3, 2, 24)
    const float* bhhR = (const float*)d_in[8];   // (3, 2, 24)
    const float* l1w  = (const float*)d_in[9];
    const float* l1b  = (const float*)d_in[10];
    const float* l2w  = (const float*)d_in[11];
    const float* l2b  = (const float*)d_in[12];
    float* out = (float*)d_out;

    float *bufA, *bufB;
    cudaGetSymbolAddress((void**)&bufA, g_bufA);
    cudaGetSymbolAddress((void**)&bufB, g_bufB);

    const int BLK_FULL = 2 * (NSEQ / 16);   // 1600 blocks (fwd + bwd)
    const int BLK_HEAD = NSEQ / 16;         // 800 blocks (fwd only)
    const int SMEM8  = 2 * CHUNK_T * 16 * (8 * 4 + 16);    // 24576
    const int SMEM16 = 2 * CHUNK_T * 16 * (16 * 4 + 16);   // 40960

    // Layer 0: raw -> bufA
    gru_layer_kernel<8, true, false><<<BLK_FULL, 128, SMEM8>>>(
        raw, bufA, Wih0, Whh0, bih0, bhh0, 192,
        nullptr, nullptr, nullptr, nullptr, nullptr);

    // Layer 1: bufA -> bufB
    gru_layer_kernel<16, false, false><<<BLK_FULL, 128, SMEM16>>>(
        bufA, bufB, WihR + 0 * 768, WhhR + 0 * 384, bihR + 0 * 48, bhhR + 0 * 48, 384,
        nullptr, nullptr, nullptr, nullptr, nullptr);

    // Layer 2: bufB -> bufA
    gru_layer_kernel<16, false, false><<<BLK_FULL, 128, SMEM16>>>(
        bufB, bufA, WihR + 1 * 768, WhhR + 1 * 384, bihR + 1 * 48, bhhR + 1 * 48, 384,
        nullptr, nullptr, nullptr, nullptr, nullptr);

    // Layer 3 + head: bufA -> out
    gru_layer_kernel<16, false, true><<<BLK_HEAD, 128, SMEM16>>>(
        bufA, nullptr, WihR + 2 * 768, WhhR + 2 * 384, bihR + 2 * 48, bhhR + 2 * 48, 384,
        l1w, l1b, l2w, l2b, out);
}